// round 15
// baseline (speedup 1.0000x reference)
#include <cuda_runtime.h>
#include <cstdint>

// FourierBlock: out = irfft3bins( einsum(rfft(q)[bins 1,4,5], W1+iW2) )
// q: (B=8, N=2000, L=64, H=4, E=16); weights (N,H,E,E,3). k,v,mask unused.
//
// Column-pair DFT: one batch per 64-thread group, 8 groups/node over 2 CTAs.
// R14: first q LDG burst issued BEFORE weight staging (hides CTA-prologue
// latency); q via __ldcs / out via __stcs (evict-first: protect weight L2
// residency shared with the sibling half-CTA).

#define NB 8
#define NN 2000
#define SLAB 4096
#define WNODE 3072
#define WHP2 776           // per-h stride in float2 units (768 + 8 pad)

// cos(2*pi*k/64); sin(2*pi*k/64) = COS64[(k+48)&63]
__device__ const float COS64[64] = {
     1.000000000f,  0.995184727f,  0.980785280f,  0.956940336f,
     0.923879533f,  0.881921264f,  0.831469612f,  0.773010453f,
     0.707106781f,  0.634393284f,  0.555570233f,  0.471396737f,
     0.382683432f,  0.290284677f,  0.195090322f,  0.098017140f,
     0.000000000f, -0.098017140f, -0.195090322f, -0.290284677f,
    -0.382683432f, -0.471396737f, -0.555570233f, -0.634393284f,
    -0.707106781f, -0.773010453f, -0.831469612f, -0.881921264f,
    -0.923879533f, -0.956940336f, -0.980785280f, -0.995184727f,
    -1.000000000f, -0.995184727f, -0.980785280f, -0.956940336f,
    -0.923879533f, -0.881921264f, -0.831469612f, -0.773010453f,
    -0.707106781f, -0.634393284f, -0.555570233f, -0.471396737f,
    -0.382683432f, -0.290284677f, -0.195090322f, -0.098017140f,
     0.000000000f,  0.098017140f,  0.195090322f,  0.290284677f,
     0.382683432f,  0.471396737f,  0.555570233f,  0.634393284f,
     0.707106781f,  0.773010453f,  0.831469612f,  0.881921264f,
     0.923879533f,  0.956940336f,  0.980785280f,  0.995184727f
};

__global__ __launch_bounds__(256, 4) void fourier_col6_kernel(
    const float* __restrict__ q,
    const float* __restrict__ w1,
    const float* __restrict__ w2,
    float* __restrict__ out)
{
    __shared__ float4 sTw4[64];           // per l: {cos t, -sin t, cos 4t, -sin 4t}
    __shared__ float2 sWc[4 * WHP2];      // [h][(m*16+i)*16 + o] = {w1, w2}
    __shared__ float2 sP[4 * 2 * 6 * 32]; // per group/warp partials: [g][w][k][c2]
    __shared__ float  sY[4][64 * 8];      // per group: 8-float records per ho

    const int half = blockIdx.x;          // 0/1 -> batches 0-3 / 4-7
    const int n    = blockIdx.y;
    const int tid  = threadIdx.x;
    const int g    = tid >> 6;            // group 0..3
    const int gtid = tid & 63;            // within group
    const int lane = tid & 31;
    const int h    = gtid >> 4;
    const int o    = gtid & 15;

    const int b = half * 4 + g;
    const size_t slab = ((size_t)b * NN + n) * SLAB;

    // ---- B setup + FIRST q burst (in flight across the whole prologue) ----
    const int rh = gtid >> 5;             // warp-in-group: rows rh*32 .. rh*32+31
    const int c2 = gtid & 31;             // float2 column (cols 2*c2, 2*c2+1)
    const float2* qp2 = (const float2*)(q + slab) + c2;
    const int rbase = rh * 32;

    float2 xa[8], xb[8];

#define LOAD8(buf, base)                                                  \
    _Pragma("unroll")                                                     \
    for (int j = 0; j < 8; ++j)                                           \
        buf[j] = __ldcs(qp2 + (size_t)(rbase + (base) + j) * 32);

    LOAD8(xa, 0)        // 8 LDG.64 outstanding before any prologue work

    // ---- init: packed analysis twiddle table (bins 1 and 4) ----
    if (tid < 64) {
        int l  = tid;
        int k1 = l & 63, k4 = (4 * l) & 63;
        sTw4[l] = make_float4(COS64[k1], -COS64[(k1 + 48) & 63],
                              COS64[k4], -COS64[(k4 + 48) & 63]);
    }

    // ---- init: weights transposed + re/im interleaved ----
    {
        const float4* a4 = (const float4*)(w1 + (size_t)n * WNODE);
        const float4* b4 = (const float4*)(w2 + (size_t)n * WNODE);
        #pragma unroll
        for (int r = 0; r < 3; ++r) {
            int g4 = tid + 256 * r;               // 0..767
            float4 av = a4[g4];
            float4 bv = b4[g4];
            const float* ap = &av.x;
            const float* bp = &bv.x;
            #pragma unroll
            for (int e = 0; e < 4; ++e) {
                int rid = 4 * g4 + e;              // h*768 + i*48 + o*3 + m
                int hh  = rid / 768;
                int r2  = rid - hh * 768;
                int ii  = r2 / 48;
                int r3  = r2 - ii * 48;
                int oo  = r3 / 3;
                int mm  = r3 - oo * 3;
                sWc[hh * WHP2 + (mm * 16 + ii) * 16 + oo] = make_float2(ap[e], bp[e]);
            }
        }
    }
    __syncthreads();

    // ---- B: column-pair DFT over this warp's 32 rows ----
    {
        float2 a0r = {0.f,0.f}, a0i = {0.f,0.f};
        float2 a1r = {0.f,0.f}, a1i = {0.f,0.f};
        float2 a2r = {0.f,0.f}, a2i = {0.f,0.f};

#define PROC8(buf, base)                                                  \
        _Pragma("unroll")                                                 \
        for (int j = 0; j < 8; ++j) {                                     \
            float2 x = buf[j];                                            \
            float4 t = sTw4[rbase + (base) + j];                          \
            float c5 = t.x * t.z - t.y * t.w;                             \
            float s5 = fmaf(t.x, t.w, t.y * t.z);                         \
            a0r.x = fmaf(x.x, t.x, a0r.x);  a0r.y = fmaf(x.y, t.x, a0r.y);\
            a0i.x = fmaf(x.x, t.y, a0i.x);  a0i.y = fmaf(x.y, t.y, a0i.y);\
            a1r.x = fmaf(x.x, t.z, a1r.x);  a1r.y = fmaf(x.y, t.z, a1r.y);\
            a1i.x = fmaf(x.x, t.w, a1i.x);  a1i.y = fmaf(x.y, t.w, a1i.y);\
            a2r.x = fmaf(x.x, c5,  a2r.x);  a2r.y = fmaf(x.y, c5,  a2r.y);\
            a2i.x = fmaf(x.x, s5,  a2i.x);  a2i.y = fmaf(x.y, s5,  a2i.y);\
        }

        LOAD8(xb, 8)        // next burst in flight while processing xa
        PROC8(xa, 0)
        LOAD8(xa, 16)
        PROC8(xb, 8)
        LOAD8(xb, 24)
        PROC8(xa, 16)
        PROC8(xb, 24)

#undef LOAD8
#undef PROC8

        // publish per-warp partials: [g][rh][k][c2]
        float2* sPp = sP + ((g * 2 + rh) * 6) * 32 + c2;
        sPp[0 * 32] = a0r;  sPp[1 * 32] = a0i;
        sPp[2 * 32] = a1r;  sPp[3 * 32] = a1i;
        sPp[4 * 32] = a2r;  sPp[5 * 32] = a2i;
    }
    asm volatile("bar.sync %0, %1;" :: "r"(g + 1), "r"(64) : "memory");

    // ---- combine the two warps' partials: thread gtid owns X[*][gtid] ----
    float xr0, xi0, xr1, xi1, xr2, xi2;
    {
        const int e  = gtid & 1;
        const int cc = gtid >> 1;
        const float* sp0 = (const float*)(sP + (g * 2 + 0) * 6 * 32);
        const float* sp1 = (const float*)(sP + (g * 2 + 1) * 6 * 32);
        xr0 = sp0[(0 * 32 + cc) * 2 + e] + sp1[(0 * 32 + cc) * 2 + e];
        xi0 = sp0[(1 * 32 + cc) * 2 + e] + sp1[(1 * 32 + cc) * 2 + e];
        xr1 = sp0[(2 * 32 + cc) * 2 + e] + sp1[(2 * 32 + cc) * 2 + e];
        xi1 = sp0[(3 * 32 + cc) * 2 + e] + sp1[(3 * 32 + cc) * 2 + e];
        xr2 = sp0[(4 * 32 + cc) * 2 + e] + sp1[(4 * 32 + cc) * 2 + e];
        xi2 = sp0[(5 * 32 + cc) * 2 + e] + sp1[(5 * 32 + cc) * 2 + e];
    }

    // ---- C: complex 16x16 mix via warp shuffles + float2 weight loads ----
    float yr0 = 0.f, yi1r = 0.f, yi1i = 0.f, yi2r = 0.f, yi2i = 0.f;
    {
        const int sb = lane & 16;
        const float2* wP = sWc + h * WHP2 + o;
        #pragma unroll
        for (int i = 0; i < 16; ++i) {
            int src = sb | i;
            float a0 = __shfl_sync(0xffffffffu, xr0, src);
            float b0 = __shfl_sync(0xffffffffu, xi0, src);
            float a1 = __shfl_sync(0xffffffffu, xr1, src);
            float b1 = __shfl_sync(0xffffffffu, xi1, src);
            float a2 = __shfl_sync(0xffffffffu, xr2, src);
            float b2 = __shfl_sync(0xffffffffu, xi2, src);
            float2 w0  = wP[(0 * 16 + i) * 16];
            float2 w1v = wP[(1 * 16 + i) * 16];
            float2 w2v = wP[(2 * 16 + i) * 16];
            // bin 0: only the real part survives irfft
            yr0  = fmaf(a0, w0.x, yr0);    yr0  = fmaf(-b0, w0.y, yr0);
            yi1r = fmaf(a1, w1v.x, yi1r);  yi1r = fmaf(-b1, w1v.y, yi1r);
            yi1i = fmaf(a1, w1v.y, yi1i);  yi1i = fmaf( b1, w1v.x, yi1i);
            yi2r = fmaf(a2, w2v.x, yi2r);  yi2r = fmaf(-b2, w2v.y, yi2r);
            yi2i = fmaf(a2, w2v.y, yi2i);  yi2i = fmaf( b2, w2v.x, yi2i);
        }
    }

    // ---- publish Y record (prescaled), group-local barrier ----
    {
        float* rec = sY[g] + gtid * 8;
        *(float4*)rec = make_float4(yr0 * 0.015625f, yi1r * 0.03125f,
                                    yi1i * 0.03125f, yi2r * 0.03125f);
        rec[4] = yi2i * 0.03125f;
    }
    asm volatile("bar.sync %0, %1;" :: "r"(g + 1), "r"(64) : "memory");

    // ---- D: 3-bin synthesis; twiddle recurrence; streaming STG.128 ----
    float c1b, s1b, c2b, s2b;
    {
        int l0 = (gtid & 15) << 2;
        int l2 = (2 * l0) & 63;
        c1b = COS64[l0];  s1b = COS64[(l0 + 48) & 63];
        c2b = COS64[l2];  s2b = COS64[(l2 + 48) & 63];
    }
    const float R1C = 0.995184727f, R1S = 0.098017140f;   // e^{+i*2pi/64}
    const float R2C = 0.980785280f, R2S = 0.195090322f;   // e^{+i*4pi/64}
    {
        const float* sy = sY[g];
        float4* o4 = (float4*)(out + slab);
        #pragma unroll
        for (int r = 0; r < 16; ++r) {
            int f4i = gtid + (r << 6);
            int hd  = f4i >> 4;
            const float* rec = sy + hd * 8;
            float4 ya  = *(const float4*)rec;   // {y0, y1r, y1i, y2r}
            float  y2i = rec[4];
            float cc1 = c1b, ss1 = s1b, cc2 = c2b, ss2 = s2b;
            float4 vv;  float* vp = &vv.x;
            #pragma unroll
            for (int j = 0; j < 4; ++j) {
                float acc = ya.x;
                acc = fmaf(ya.y, cc1, acc);  acc = fmaf(-ya.z, ss1, acc);
                acc = fmaf(ya.w, cc2, acc);  acc = fmaf(-y2i, ss2, acc);
                vp[j] = acc;
                if (j < 3) {
                    float t;
                    t = fmaf(cc1, R1C, -ss1 * R1S);  ss1 = fmaf(ss1, R1C, cc1 * R1S);  cc1 = t;
                    t = fmaf(cc2, R2C, -ss2 * R2S);  ss2 = fmaf(ss2, R2C, cc2 * R2S);  cc2 = t;
                }
            }
            __stcs(o4 + f4i, vv);
        }
    }
}

extern "C" void kernel_launch(void* const* d_in, const int* in_sizes, int n_in,
                              void* d_out, int out_size)
{
    // metadata order: q, k, v, mask, weights1, weights2 (k, v, mask unused)
    const float* q  = (const float*)d_in[0];
    const float* w1 = (const float*)d_in[4];
    const float* w2 = (const float*)d_in[5];
    float* out = (float*)d_out;

    dim3 grid(2, NN);   // the two half-CTAs of a node adjacent for L2 reuse
    fourier_col6_kernel<<<grid, 256>>>(q, w1, w2, out);
}

// round 16
// speedup vs baseline: 1.0358x; 1.0358x over previous
#include <cuda_runtime.h>
#include <cstdint>

// FourierBlock: out = irfft3bins( einsum(rfft(q)[bins 1,4,5], W1+iW2) )
// q: (B=8, N=2000, L=64, H=4, E=16); weights (N,H,E,E,3). k,v,mask unused.
//
// Column-pair DFT: one batch per 64-thread group, 8 groups/node over 2 CTAs.
// R15 = R13 structure (plain loads/stores — R14's cache hints reverted) plus
// the first q LDG burst hoisted above weight staging to hide the CTA prologue.

#define NB 8
#define NN 2000
#define SLAB 4096
#define WNODE 3072
#define WHP2 776           // per-h stride in float2 units (768 + 8 pad)

// cos(2*pi*k/64); sin(2*pi*k/64) = COS64[(k+48)&63]
__device__ const float COS64[64] = {
     1.000000000f,  0.995184727f,  0.980785280f,  0.956940336f,
     0.923879533f,  0.881921264f,  0.831469612f,  0.773010453f,
     0.707106781f,  0.634393284f,  0.555570233f,  0.471396737f,
     0.382683432f,  0.290284677f,  0.195090322f,  0.098017140f,
     0.000000000f, -0.098017140f, -0.195090322f, -0.290284677f,
    -0.382683432f, -0.471396737f, -0.555570233f, -0.634393284f,
    -0.707106781f, -0.773010453f, -0.831469612f, -0.881921264f,
    -0.923879533f, -0.956940336f, -0.980785280f, -0.995184727f,
    -1.000000000f, -0.995184727f, -0.980785280f, -0.956940336f,
    -0.923879533f, -0.881921264f, -0.831469612f, -0.773010453f,
    -0.707106781f, -0.634393284f, -0.555570233f, -0.471396737f,
    -0.382683432f, -0.290284677f, -0.195090322f, -0.098017140f,
     0.000000000f,  0.098017140f,  0.195090322f,  0.290284677f,
     0.382683432f,  0.471396737f,  0.555570233f,  0.634393284f,
     0.707106781f,  0.773010453f,  0.831469612f,  0.881921264f,
     0.923879533f,  0.956940336f,  0.980785280f,  0.995184727f
};

__global__ __launch_bounds__(256, 4) void fourier_col7_kernel(
    const float* __restrict__ q,
    const float* __restrict__ w1,
    const float* __restrict__ w2,
    float* __restrict__ out)
{
    __shared__ float4 sTw4[64];           // per l: {cos t, -sin t, cos 4t, -sin 4t}
    __shared__ float2 sWc[4 * WHP2];      // [h][(m*16+i)*16 + o] = {w1, w2}
    __shared__ float2 sP[4 * 2 * 6 * 32]; // per group/warp partials: [g][w][k][c2]
    __shared__ float  sY[4][64 * 8];      // per group: 8-float records per ho

    const int half = blockIdx.x;          // 0/1 -> batches 0-3 / 4-7
    const int n    = blockIdx.y;
    const int tid  = threadIdx.x;
    const int g    = tid >> 6;            // group 0..3
    const int gtid = tid & 63;            // within group
    const int lane = tid & 31;
    const int h    = gtid >> 4;
    const int o    = gtid & 15;

    const int b = half * 4 + g;
    const size_t slab = ((size_t)b * NN + n) * SLAB;

    // ---- B setup + FIRST q burst (in flight across the whole prologue) ----
    const int rh = gtid >> 5;             // warp-in-group: rows rh*32 .. rh*32+31
    const int c2 = gtid & 31;             // float2 column (cols 2*c2, 2*c2+1)
    const float2* qp2 = (const float2*)(q + slab) + c2;
    const int rbase = rh * 32;

    float2 xa[8], xb[8];

#define LOAD8(buf, base)                                                  \
    _Pragma("unroll")                                                     \
    for (int j = 0; j < 8; ++j)                                           \
        buf[j] = __ldg(qp2 + (size_t)(rbase + (base) + j) * 32);

    LOAD8(xa, 0)        // 8 LDG.64 outstanding before any prologue work

    // ---- init: packed analysis twiddle table (bins 1 and 4) ----
    if (tid < 64) {
        int l  = tid;
        int k1 = l & 63, k4 = (4 * l) & 63;
        sTw4[l] = make_float4(COS64[k1], -COS64[(k1 + 48) & 63],
                              COS64[k4], -COS64[(k4 + 48) & 63]);
    }

    // ---- init: weights transposed + re/im interleaved ----
    {
        const float4* a4 = (const float4*)(w1 + (size_t)n * WNODE);
        const float4* b4 = (const float4*)(w2 + (size_t)n * WNODE);
        #pragma unroll
        for (int r = 0; r < 3; ++r) {
            int g4 = tid + 256 * r;               // 0..767
            float4 av = a4[g4];
            float4 bv = b4[g4];
            const float* ap = &av.x;
            const float* bp = &bv.x;
            #pragma unroll
            for (int e = 0; e < 4; ++e) {
                int rid = 4 * g4 + e;              // h*768 + i*48 + o*3 + m
                int hh  = rid / 768;
                int r2  = rid - hh * 768;
                int ii  = r2 / 48;
                int r3  = r2 - ii * 48;
                int oo  = r3 / 3;
                int mm  = r3 - oo * 3;
                sWc[hh * WHP2 + (mm * 16 + ii) * 16 + oo] = make_float2(ap[e], bp[e]);
            }
        }
    }
    __syncthreads();

    // ---- B: column-pair DFT over this warp's 32 rows ----
    {
        float2 a0r = {0.f,0.f}, a0i = {0.f,0.f};
        float2 a1r = {0.f,0.f}, a1i = {0.f,0.f};
        float2 a2r = {0.f,0.f}, a2i = {0.f,0.f};

#define PROC8(buf, base)                                                  \
        _Pragma("unroll")                                                 \
        for (int j = 0; j < 8; ++j) {                                     \
            float2 x = buf[j];                                            \
            float4 t = sTw4[rbase + (base) + j];                          \
            float c5 = t.x * t.z - t.y * t.w;                             \
            float s5 = fmaf(t.x, t.w, t.y * t.z);                         \
            a0r.x = fmaf(x.x, t.x, a0r.x);  a0r.y = fmaf(x.y, t.x, a0r.y);\
            a0i.x = fmaf(x.x, t.y, a0i.x);  a0i.y = fmaf(x.y, t.y, a0i.y);\
            a1r.x = fmaf(x.x, t.z, a1r.x);  a1r.y = fmaf(x.y, t.z, a1r.y);\
            a1i.x = fmaf(x.x, t.w, a1i.x);  a1i.y = fmaf(x.y, t.w, a1i.y);\
            a2r.x = fmaf(x.x, c5,  a2r.x);  a2r.y = fmaf(x.y, c5,  a2r.y);\
            a2i.x = fmaf(x.x, s5,  a2i.x);  a2i.y = fmaf(x.y, s5,  a2i.y);\
        }

        LOAD8(xb, 8)        // next burst in flight while processing xa
        PROC8(xa, 0)
        LOAD8(xa, 16)
        PROC8(xb, 8)
        LOAD8(xb, 24)
        PROC8(xa, 16)
        PROC8(xb, 24)

#undef LOAD8
#undef PROC8

        // publish per-warp partials: [g][rh][k][c2]
        float2* sPp = sP + ((g * 2 + rh) * 6) * 32 + c2;
        sPp[0 * 32] = a0r;  sPp[1 * 32] = a0i;
        sPp[2 * 32] = a1r;  sPp[3 * 32] = a1i;
        sPp[4 * 32] = a2r;  sPp[5 * 32] = a2i;
    }
    asm volatile("bar.sync %0, %1;" :: "r"(g + 1), "r"(64) : "memory");

    // ---- combine the two warps' partials: thread gtid owns X[*][gtid] ----
    float xr0, xi0, xr1, xi1, xr2, xi2;
    {
        const int e  = gtid & 1;
        const int cc = gtid >> 1;
        const float* sp0 = (const float*)(sP + (g * 2 + 0) * 6 * 32);
        const float* sp1 = (const float*)(sP + (g * 2 + 1) * 6 * 32);
        xr0 = sp0[(0 * 32 + cc) * 2 + e] + sp1[(0 * 32 + cc) * 2 + e];
        xi0 = sp0[(1 * 32 + cc) * 2 + e] + sp1[(1 * 32 + cc) * 2 + e];
        xr1 = sp0[(2 * 32 + cc) * 2 + e] + sp1[(2 * 32 + cc) * 2 + e];
        xi1 = sp0[(3 * 32 + cc) * 2 + e] + sp1[(3 * 32 + cc) * 2 + e];
        xr2 = sp0[(4 * 32 + cc) * 2 + e] + sp1[(4 * 32 + cc) * 2 + e];
        xi2 = sp0[(5 * 32 + cc) * 2 + e] + sp1[(5 * 32 + cc) * 2 + e];
    }

    // ---- C: complex 16x16 mix via warp shuffles + float2 weight loads ----
    float yr0 = 0.f, yi1r = 0.f, yi1i = 0.f, yi2r = 0.f, yi2i = 0.f;
    {
        const int sb = lane & 16;
        const float2* wP = sWc + h * WHP2 + o;
        #pragma unroll
        for (int i = 0; i < 16; ++i) {
            int src = sb | i;
            float a0 = __shfl_sync(0xffffffffu, xr0, src);
            float b0 = __shfl_sync(0xffffffffu, xi0, src);
            float a1 = __shfl_sync(0xffffffffu, xr1, src);
            float b1 = __shfl_sync(0xffffffffu, xi1, src);
            float a2 = __shfl_sync(0xffffffffu, xr2, src);
            float b2 = __shfl_sync(0xffffffffu, xi2, src);
            float2 w0  = wP[(0 * 16 + i) * 16];
            float2 w1v = wP[(1 * 16 + i) * 16];
            float2 w2v = wP[(2 * 16 + i) * 16];
            // bin 0: only the real part survives irfft
            yr0  = fmaf(a0, w0.x, yr0);    yr0  = fmaf(-b0, w0.y, yr0);
            yi1r = fmaf(a1, w1v.x, yi1r);  yi1r = fmaf(-b1, w1v.y, yi1r);
            yi1i = fmaf(a1, w1v.y, yi1i);  yi1i = fmaf( b1, w1v.x, yi1i);
            yi2r = fmaf(a2, w2v.x, yi2r);  yi2r = fmaf(-b2, w2v.y, yi2r);
            yi2i = fmaf(a2, w2v.y, yi2i);  yi2i = fmaf( b2, w2v.x, yi2i);
        }
    }

    // ---- publish Y record (prescaled), group-local barrier ----
    {
        float* rec = sY[g] + gtid * 8;
        *(float4*)rec = make_float4(yr0 * 0.015625f, yi1r * 0.03125f,
                                    yi1i * 0.03125f, yi2r * 0.03125f);
        rec[4] = yi2i * 0.03125f;
    }
    asm volatile("bar.sync %0, %1;" :: "r"(g + 1), "r"(64) : "memory");

    // ---- D: 3-bin synthesis; base twiddles + in-loop rotation; STG.128 ----
    float c1b, s1b, c2b, s2b;
    {
        int l0 = (gtid & 15) << 2;
        int l2 = (2 * l0) & 63;
        c1b = COS64[l0];  s1b = COS64[(l0 + 48) & 63];
        c2b = COS64[l2];  s2b = COS64[(l2 + 48) & 63];
    }
    const float R1C = 0.995184727f, R1S = 0.098017140f;   // e^{+i*2pi/64}
    const float R2C = 0.980785280f, R2S = 0.195090322f;   // e^{+i*4pi/64}
    {
        const float* sy = sY[g];
        float4* o4 = (float4*)(out + slab);
        #pragma unroll
        for (int r = 0; r < 16; ++r) {
            int f4i = gtid + (r << 6);
            int hd  = f4i >> 4;
            const float* rec = sy + hd * 8;
            float4 ya  = *(const float4*)rec;   // {y0, y1r, y1i, y2r}
            float  y2i = rec[4];
            float cc1 = c1b, ss1 = s1b, cc2 = c2b, ss2 = s2b;
            float4 vv;  float* vp = &vv.x;
            #pragma unroll
            for (int j = 0; j < 4; ++j) {
                float acc = ya.x;
                acc = fmaf(ya.y, cc1, acc);  acc = fmaf(-ya.z, ss1, acc);
                acc = fmaf(ya.w, cc2, acc);  acc = fmaf(-y2i, ss2, acc);
                vp[j] = acc;
                if (j < 3) {
                    float t;
                    t = fmaf(cc1, R1C, -ss1 * R1S);  ss1 = fmaf(ss1, R1C, cc1 * R1S);  cc1 = t;
                    t = fmaf(cc2, R2C, -ss2 * R2S);  ss2 = fmaf(ss2, R2C, cc2 * R2S);  cc2 = t;
                }
            }
            o4[f4i] = vv;
        }
    }
}

extern "C" void kernel_launch(void* const* d_in, const int* in_sizes, int n_in,
                              void* d_out, int out_size)
{
    // metadata order: q, k, v, mask, weights1, weights2 (k, v, mask unused)
    const float* q  = (const float*)d_in[0];
    const float* w1 = (const float*)d_in[4];
    const float* w2 = (const float*)d_in[5];
    float* out = (float*)d_out;

    dim3 grid(2, NN);   // the two half-CTAs of a node adjacent for L2 reuse
    fourier_col7_kernel<<<grid, 256>>>(q, w1, w2, out);
}